// round 12
// baseline (speedup 1.0000x reference)
#include <cuda_runtime.h>
#include <cstdint>

#define BATCH   4
#define TSEQ    4096
#define CDIM    512
#define HDIM    64
#define BT_TOTAL (BATCH * TSEQ)   // 16384
#define QTILE   128
#define KTILE   32
#define NSPLIT  2
#define KEYS_PER_SPLIT (TSEQ / NSPLIT)     // 2048
#define NT      (KEYS_PER_SPLIT / KTILE)   // 64

#define KSTR4   36   // K row stride (float4): 32 entries used
#define VSTR2   20   // V^T row stride (float2): 16 entries used
#define KBUF4   1152 // K buffer size (float4)
#define VBUF2   1280 // V buffer size (float2)
#define WSTR4   20   // W row stride (float4)
#define XSTR    36   // xs row stride (floats)

typedef unsigned long long u64;

// ---- tf32 helpers ----
__device__ __forceinline__ float tf32_hi(float a) {
    unsigned u;
    asm("cvt.rna.tf32.f32 %0, %1;" : "=r"(u) : "f"(a));
    return __uint_as_float(u);
}
__device__ __forceinline__ void mma_tf32(
    float& c0, float& c1, float& c2, float& c3,
    float a0, float a1, float a2, float a3,
    float b0, float b1)
{
    unsigned A0 = __float_as_uint(a0), A1 = __float_as_uint(a1);
    unsigned A2 = __float_as_uint(a2), A3 = __float_as_uint(a3);
    unsigned B0 = __float_as_uint(b0), B1 = __float_as_uint(b1);
    asm("mma.sync.aligned.m16n8k8.row.col.f32.tf32.tf32.f32 "
        "{%0,%1,%2,%3},{%4,%5,%6,%7},{%8,%9},{%0,%1,%2,%3};"
        : "+f"(c0), "+f"(c1), "+f"(c2), "+f"(c3)
        : "r"(A0), "r"(A1), "r"(A2), "r"(A3), "r"(B0), "r"(B1));
}

// Scratch (static device arrays per allocation rules).
__device__ float g_q[BT_TOTAL * HDIM];
__device__ float g_k[BT_TOTAL * HDIM];
__device__ float g_v[BT_TOTAL * HDIM];
__device__ float g_wt[3][HDIM][CDIM];      // transposed weights [mat][n][k]
// split-KV partials
__device__ float g_pacc[NSPLIT][BT_TOTAL][HDIM];
__device__ float g_pm[NSPLIT][BT_TOTAL];
__device__ float g_pl[NSPLIT][BT_TOTAL];

// ---------------------------------------------------------------------------
// Transpose W [512][64] -> g_wt [64][512].  grid (128, 3), block 256.
// ---------------------------------------------------------------------------
__global__ __launch_bounds__(256) void transpose_w_kernel(
    const float* __restrict__ Wq,
    const float* __restrict__ Wk,
    const float* __restrict__ Wv)
{
    const int mat = blockIdx.y;
    const float* __restrict__ W = (mat == 0) ? Wq : (mat == 1) ? Wk : Wv;
    const int idx = blockIdx.x * 256 + threadIdx.x;   // 0..32767
    const int k = idx & (CDIM - 1);
    const int n = idx >> 9;
    g_wt[mat][n][k] = W[k * HDIM + n];
}

// ---------------------------------------------------------------------------
// Tensor-core projection GEMM, 3xTF32 (unchanged from R10).
// ---------------------------------------------------------------------------
__global__ __launch_bounds__(128) void proj_mma_kernel(const float* __restrict__ x)
{
    __shared__ float  xs[128 * XSTR];
    __shared__ float4 Wsm[HDIM * WSTR4];

    const int mat  = blockIdx.y;
    float* __restrict__ out = (mat == 0) ? g_q : (mat == 1) ? g_k : g_v;
    const int row0 = blockIdx.x * 128;
    const int tid  = threadIdx.x;
    const int w    = tid >> 5;
    const int ln   = tid & 31;
    const int g    = ln >> 2;
    const int tg   = ln & 3;

    float o[2][8][4];
    #pragma unroll
    for (int m = 0; m < 2; m++)
        #pragma unroll
        for (int n = 0; n < 8; n++)
            #pragma unroll
            for (int i = 0; i < 4; i++) o[m][n][i] = 0.0f;

    #pragma unroll 1
    for (int k0 = 0; k0 < CDIM; k0 += 32) {
        __syncthreads();
        #pragma unroll
        for (int p = 0; p < 8; p++) {
            const int task = p * 128 + tid;
            const int r    = task >> 3;
            const int cg   = task & 7;
            float4 v = *reinterpret_cast<const float4*>(
                &x[(long)(row0 + r) * CDIM + k0 + cg * 4]);
            *reinterpret_cast<float4*>(&xs[r * XSTR + cg * 4]) = v;
        }
        #pragma unroll
        for (int p = 0; p < 2; p++) {
            const int task = p * 128 + tid;
            const int n    = task >> 2;
            const int c    = task & 3;
            const float* wr = &g_wt[mat][n][k0 + c * 8];
            float4 fa = *reinterpret_cast<const float4*>(wr);
            float4 fb = *reinterpret_cast<const float4*>(wr + 4);
            float a_[4] = {fa.x, fa.y, fa.z, fa.w};
            float b_[4] = {fb.x, fb.y, fb.z, fb.w};
            float4* dst = &Wsm[n * WSTR4 + c * 4];
            #pragma unroll
            for (int q = 0; q < 4; q++) {
                float ha = tf32_hi(a_[q]);
                float hb = tf32_hi(b_[q]);
                dst[q] = make_float4(ha, hb, a_[q] - ha, b_[q] - hb);
            }
        }
        __syncthreads();

        #pragma unroll
        for (int kb = 0; kb < 4; kb++) {
            float ah[2][4], al[2][4];
            #pragma unroll
            for (int m = 0; m < 2; m++) {
                const int r = w * 32 + m * 16 + g;
                float a0 = xs[r * XSTR + kb * 8 + tg];
                float a1 = xs[(r + 8) * XSTR + kb * 8 + tg];
                float a2 = xs[r * XSTR + kb * 8 + tg + 4];
                float a3 = xs[(r + 8) * XSTR + kb * 8 + tg + 4];
                ah[m][0] = tf32_hi(a0); al[m][0] = a0 - ah[m][0];
                ah[m][1] = tf32_hi(a1); al[m][1] = a1 - ah[m][1];
                ah[m][2] = tf32_hi(a2); al[m][2] = a2 - ah[m][2];
                ah[m][3] = tf32_hi(a3); al[m][3] = a3 - ah[m][3];
            }
            #pragma unroll
            for (int n = 0; n < 8; n++) {
                float4 wp = Wsm[(n * 8 + g) * WSTR4 + kb * 4 + tg];
                #pragma unroll
                for (int m = 0; m < 2; m++) {
                    mma_tf32(o[m][n][0], o[m][n][1], o[m][n][2], o[m][n][3],
                             ah[m][0], ah[m][1], ah[m][2], ah[m][3], wp.x, wp.y);
                    mma_tf32(o[m][n][0], o[m][n][1], o[m][n][2], o[m][n][3],
                             al[m][0], al[m][1], al[m][2], al[m][3], wp.x, wp.y);
                    mma_tf32(o[m][n][0], o[m][n][1], o[m][n][2], o[m][n][3],
                             ah[m][0], ah[m][1], ah[m][2], ah[m][3], wp.z, wp.w);
                }
            }
        }
    }

    const float scale = (mat == 0) ? 8.0f : 1.0f;
    #pragma unroll
    for (int m = 0; m < 2; m++) {
        const long rowA = (long)(row0 + w * 32 + m * 16 + g);
        const long rowB = rowA + 8;
        #pragma unroll
        for (int n = 0; n < 8; n++) {
            const int c = n * 8 + 2 * tg;
            *reinterpret_cast<float2*>(&out[rowA * HDIM + c]) =
                make_float2(o[m][n][0] * scale, o[m][n][1] * scale);
            *reinterpret_cast<float2*>(&out[rowB * HDIM + c]) =
                make_float2(o[m][n][2] * scale, o[m][n][3] * scale);
        }
    }
}

// ---------------------------------------------------------------------------
// mma.sync flash attention. QK = 3xTF32, PV = 1xTF32.
// Double-buffered K/V smem: ONE __syncthreads per tile; staging of t+1
// overlaps compute of t within and across warps. Register prefetch of t+2.
// grid (TSEQ/QTILE, BATCH, NSPLIT), block 128.
// smem: KP4 2x1152 f4 | VP2 2x1280 f2 | QA 2048 f4 | P2 2048 f2 = 106,496 B.
// ---------------------------------------------------------------------------
__global__ __launch_bounds__(128) void attn_mma_kernel()
{
    extern __shared__ float4 sm4[];
    float4* KP4 = sm4;                                     // 2*KBUF4 f4
    float2* VP2 = reinterpret_cast<float2*>(sm4 + 2304);   // 2*VBUF2 f2
    float4* QA  = sm4 + 3584;                              // 2048 f4
    float2* P2  = reinterpret_cast<float2*>(sm4 + 5632);   // 2048 f2

    const int b     = blockIdx.y;
    const int split = blockIdx.z;
    const int q0    = blockIdx.x * QTILE;
    const int tid   = threadIdx.x;
    const int w     = tid >> 5;
    const int ln    = tid & 31;
    const int g     = ln >> 2;
    const int tg    = ln & 3;

    const float* __restrict__ kb = &g_k[(long)b * TSEQ * HDIM];
    const float* __restrict__ vb = &g_v[(long)b * TSEQ * HDIM];

    // K staging indices
    const int kkey0 = tid >> 3;
    const int kc0   = tid & 7;
    const int kkey1 = (128 + tid) >> 3;
    const int kc1   = (128 + tid) & 7;
    // V staging indices
    int vkeyA[2], vh4[2], vkk[2], vtt[2];
    #pragma unroll
    for (int p = 0; p < 2; p++) {
        const int task = p * 128 + tid;
        const int bk   = task >> 4;
        vh4[p] = (task & 15) * 4;
        vkk[p] = bk >> 2;
        vtt[p] = bk & 3;
        vkeyA[p] = vkk[p] * 8 + vtt[p];
    }

    // ---- stage Q (raw, A-fragment packed) ----
    #pragma unroll
    for (int i = 0; i < 16; i++) {
        const int e  = tid * 16 + i;
        const int mb = e >> 8;
        const int k  = (e >> 5) & 7;
        const int t2 = (e >> 3) & 3;
        const int g2 = e & 7;
        const int r  = (mb >> 1) * 32 + (mb & 1) * 16 + g2;
        const int c  = k * 8 + t2;
        const float* q0p = &g_q[((long)b * TSEQ + q0 + r) * HDIM];
        const float* q1p = &g_q[((long)b * TSEQ + q0 + r + 8) * HDIM];
        QA[e] = make_float4(q0p[c], q1p[c], q0p[c + 4], q1p[c + 4]);
    }

    float o[2][8][4];
    #pragma unroll
    for (int m = 0; m < 2; m++)
        #pragma unroll
        for (int n = 0; n < 8; n++)
            #pragma unroll
            for (int i = 0; i < 4; i++) o[m][n][i] = 0.0f;
    float mr[2][2], lr[2][2];
    #pragma unroll
    for (int m = 0; m < 2; m++) {
        mr[m][0] = mr[m][1] = -1e30f;
        lr[m][0] = lr[m][1] = 0.0f;
    }

    float4 kfa[2], kfb[2], vfa[2], vfb[2];

    // write staged tile from regs into buffer `buf`
    auto write_tile = [&](int buf) {
        float4* Kd = KP4 + buf * KBUF4;
        float2* Vd = VP2 + buf * VBUF2;
        #pragma unroll
        for (int p = 0; p < 2; p++) {
            const int key = p ? kkey1 : kkey0;
            const int c   = p ? kc1 : kc0;
            float4 fa = kfa[p], fb = kfb[p];
            float a_[4] = {fa.x, fa.y, fa.z, fa.w};
            float b_[4] = {fb.x, fb.y, fb.z, fb.w};
            float4* dst = &Kd[key * KSTR4 + c * 4];
            #pragma unroll
            for (int q = 0; q < 4; q++) {
                float ha = tf32_hi(a_[q]);
                float hb = tf32_hi(b_[q]);
                dst[q] = make_float4(ha, hb, a_[q] - ha, b_[q] - hb);
            }
        }
        #pragma unroll
        for (int p = 0; p < 2; p++) {
            float4 fa = vfa[p], fb = vfb[p];
            float a_[4] = {fa.x, fa.y, fa.z, fa.w};
            float b_[4] = {fb.x, fb.y, fb.z, fb.w};
            #pragma unroll
            for (int q = 0; q < 4; q++) {
                Vd[(vh4[p] + q) * VSTR2 + vkk[p] * 4 + vtt[p]] =
                    make_float2(tf32_hi(a_[q]), tf32_hi(b_[q]));
            }
        }
    };
    // prefetch global tile `t` into registers
    auto prefetch = [&](int t) {
        const int t0 = split * KEYS_PER_SPLIT + t * KTILE;
        kfa[0] = *reinterpret_cast<const float4*>(&kb[(long)(t0 + kkey0) * HDIM + kc0 * 8]);
        kfb[0] = *reinterpret_cast<const float4*>(&kb[(long)(t0 + kkey0) * HDIM + kc0 * 8 + 4]);
        kfa[1] = *reinterpret_cast<const float4*>(&kb[(long)(t0 + kkey1) * HDIM + kc1 * 8]);
        kfb[1] = *reinterpret_cast<const float4*>(&kb[(long)(t0 + kkey1) * HDIM + kc1 * 8 + 4]);
        #pragma unroll
        for (int p = 0; p < 2; p++) {
            vfa[p] = *reinterpret_cast<const float4*>(&vb[(long)(t0 + vkeyA[p]) * HDIM + vh4[p]]);
            vfb[p] = *reinterpret_cast<const float4*>(&vb[(long)(t0 + vkeyA[p] + 4) * HDIM + vh4[p]]);
        }
    };

    // ---- prologue: tile 0 into buf 0, tile 1 into regs ----
    prefetch(0);
    write_tile(0);
    prefetch(1);
    __syncthreads();

    #pragma unroll 1
    for (int t = 0; t < NT; t++) {
        const int cur = t & 1;
        // stage t+1 into the other buffer (its last readers finished at t-1,
        // protected by the end-of-tile barrier), then prefetch t+2.
        if (t + 1 < NT) {
            write_tile((t + 1) & 1);
            if (t + 2 < NT) prefetch(t + 2);
        }

        const float4* Kc = KP4 + cur * KBUF4;
        const float2* Vc = VP2 + cur * VBUF2;

        // ---- QK: S = Q K^T (3xTF32) ----
        float s[2][4][4];
        #pragma unroll
        for (int m = 0; m < 2; m++)
            #pragma unroll
            for (int n = 0; n < 4; n++)
                #pragma unroll
                for (int i = 0; i < 4; i++) s[m][n][i] = 0.0f;

        #pragma unroll
        for (int k = 0; k < 8; k++) {
            float qh[2][4], ql[2][4];
            #pragma unroll
            for (int m = 0; m < 2; m++) {
                float4 qa = QA[(w * 2 + m) * 256 + k * 32 + tg * 8 + g];
                float v_[4] = {qa.x, qa.y, qa.z, qa.w};
                #pragma unroll
                for (int q = 0; q < 4; q++) {
                    qh[m][q] = tf32_hi(v_[q]);
                    ql[m][q] = v_[q] - qh[m][q];
                }
            }
            const float4* kbase = &Kc[g * KSTR4 + k * 4 + tg];
            #pragma unroll
            for (int n = 0; n < 4; n++) {
                float4 kp = kbase[n * 8 * KSTR4];
                #pragma unroll
                for (int m = 0; m < 2; m++) {
                    mma_tf32(s[m][n][0], s[m][n][1], s[m][n][2], s[m][n][3],
                             qh[m][0], qh[m][1], qh[m][2], qh[m][3], kp.x, kp.y);
                    mma_tf32(s[m][n][0], s[m][n][1], s[m][n][2], s[m][n][3],
                             ql[m][0], ql[m][1], ql[m][2], ql[m][3], kp.x, kp.y);
                    mma_tf32(s[m][n][0], s[m][n][1], s[m][n][2], s[m][n][3],
                             qh[m][0], qh[m][1], qh[m][2], qh[m][3], kp.z, kp.w);
                }
            }
        }

        // ---- online softmax ----
        #pragma unroll
        for (int m = 0; m < 2; m++) {
            const int mb = w * 2 + m;
            float mxA = -1e30f, mxB = -1e30f;
            #pragma unroll
            for (int n = 0; n < 4; n++) {
                mxA = fmaxf(mxA, fmaxf(s[m][n][0], s[m][n][1]));
                mxB = fmaxf(mxB, fmaxf(s[m][n][2], s[m][n][3]));
            }
            mxA = fmaxf(mxA, __shfl_xor_sync(0xffffffffu, mxA, 1));
            mxA = fmaxf(mxA, __shfl_xor_sync(0xffffffffu, mxA, 2));
            mxB = fmaxf(mxB, __shfl_xor_sync(0xffffffffu, mxB, 1));
            mxB = fmaxf(mxB, __shfl_xor_sync(0xffffffffu, mxB, 2));

            const float nmA = fmaxf(mr[m][0], mxA);
            const float nmB = fmaxf(mr[m][1], mxB);
            const float alA = __expf(mr[m][0] - nmA);
            const float alB = __expf(mr[m][1] - nmB);
            mr[m][0] = nmA; mr[m][1] = nmB;

            float lsA = 0.0f, lsB = 0.0f;
            #pragma unroll
            for (int n = 0; n < 4; n++) {
                float p0 = __expf(s[m][n][0] - nmA);
                float p1 = __expf(s[m][n][1] - nmA);
                float p2 = __expf(s[m][n][2] - nmB);
                float p3 = __expf(s[m][n][3] - nmB);
                lsA += p0 + p1;
                lsB += p2 + p3;
                const int c = n * 8 + 2 * tg;
                P2[mb * 256 + c * 8 + g]       = make_float2(p0, p2);
                P2[mb * 256 + (c + 1) * 8 + g] = make_float2(p1, p3);
            }
            lsA += __shfl_xor_sync(0xffffffffu, lsA, 1);
            lsA += __shfl_xor_sync(0xffffffffu, lsA, 2);
            lsB += __shfl_xor_sync(0xffffffffu, lsB, 1);
            lsB += __shfl_xor_sync(0xffffffffu, lsB, 2);
            lr[m][0] = lr[m][0] * alA + lsA;
            lr[m][1] = lr[m][1] * alB + lsB;

            #pragma unroll
            for (int n = 0; n < 8; n++) {
                o[m][n][0] *= alA; o[m][n][1] *= alA;
                o[m][n][2] *= alB; o[m][n][3] *= alB;
            }
        }
        __syncwarp();

        // ---- PV: O += P V (1xTF32) ----
        #pragma unroll
        for (int k = 0; k < 4; k++) {
            float ah[2][4];
            #pragma unroll
            for (int m = 0; m < 2; m++) {
                const int mb = w * 2 + m;
                float2 pA = P2[mb * 256 + (k * 8 + tg) * 8 + g];
                float2 pB = P2[mb * 256 + (k * 8 + tg + 4) * 8 + g];
                ah[m][0] = tf32_hi(pA.x);
                ah[m][1] = tf32_hi(pA.y);
                ah[m][2] = tf32_hi(pB.x);
                ah[m][3] = tf32_hi(pB.y);
            }
            const float2* vbase = &Vc[g * VSTR2 + k * 4 + tg];
            #pragma unroll
            for (int n = 0; n < 8; n++) {
                float2 vp = vbase[n * 8 * VSTR2];
                #pragma unroll
                for (int m = 0; m < 2; m++) {
                    mma_tf32(o[m][n][0], o[m][n][1], o[m][n][2], o[m][n][3],
                             ah[m][0], ah[m][1], ah[m][2], ah[m][3], vp.x, vp.y);
                }
            }
        }
        __syncthreads();
    }

    // ---- epilogue: write unnormalized partials + (m, l) ----
    #pragma unroll
    for (int m = 0; m < 2; m++) {
        const long rowA = (long)b * TSEQ + q0 + w * 32 + m * 16 + g;
        const long rowB = rowA + 8;
        #pragma unroll
        for (int n = 0; n < 8; n++) {
            const int c = n * 8 + 2 * tg;
            *reinterpret_cast<float2*>(&g_pacc[split][rowA][c]) =
                make_float2(o[m][n][0], o[m][n][1]);
            *reinterpret_cast<float2*>(&g_pacc[split][rowB][c]) =
                make_float2(o[m][n][2], o[m][n][3]);
        }
        if (tg == 0) {
            g_pm[split][rowA] = mr[m][0];
            g_pl[split][rowA] = lr[m][0];
            g_pm[split][rowB] = mr[m][1];
            g_pl[split][rowB] = lr[m][1];
        }
    }
}

// ---------------------------------------------------------------------------
// Combine split-KV partials.
// ---------------------------------------------------------------------------
__global__ __launch_bounds__(128) void combine_kernel(float* __restrict__ out)
{
    const long row = (long)blockIdx.x * 128 + threadIdx.x;

    float m[NSPLIT], w[NSPLIT];
    float M = -1e30f;
    #pragma unroll
    for (int i = 0; i < NSPLIT; i++) {
        m[i] = g_pm[i][row];
        M = fmaxf(M, m[i]);
    }
    float L = 0.0f;
    #pragma unroll
    for (int i = 0; i < NSPLIT; i++) {
        w[i] = __expf(m[i] - M);
        L += w[i] * g_pl[i][row];
    }
    const float inv = 1.0f / L;

    float* __restrict__ orow = &out[row * HDIM];
    #pragma unroll
    for (int h = 0; h < HDIM; h += 4) {
        float4 a = make_float4(0.f, 0.f, 0.f, 0.f);
        #pragma unroll
        for (int i = 0; i < NSPLIT; i++) {
            float4 p = *reinterpret_cast<const float4*>(&g_pacc[i][row][h]);
            a.x += w[i] * p.x;
            a.y += w[i] * p.y;
            a.z += w[i] * p.z;
            a.w += w[i] * p.w;
        }
        a.x *= inv; a.y *= inv; a.z *= inv; a.w *= inv;
        *reinterpret_cast<float4*>(&orow[h]) = a;
    }
}

// ---------------------------------------------------------------------------
extern "C" void kernel_launch(void* const* d_in, const int* in_sizes, int n_in,
                              void* d_out, int out_size)
{
    const float* x  = (const float*)d_in[0];
    const float* Wq = (const float*)d_in[1];
    const float* Wk = (const float*)d_in[2];
    const float* Wv = (const float*)d_in[3];
    float* out = (float*)d_out;

    transpose_w_kernel<<<dim3(128, 3), 256>>>(Wq, Wk, Wv);

    proj_mma_kernel<<<dim3(BT_TOTAL / 128, 3), 128>>>(x);

    const int smem_bytes = 6656 * 16;   // 106,496 B (2 CTAs/SM: 213 KB <= 228)
    static bool attr_set = false;
    if (!attr_set) {
        cudaFuncSetAttribute(attn_mma_kernel,
                             cudaFuncAttributeMaxDynamicSharedMemorySize, smem_bytes);
        attr_set = true;
    }
    dim3 ag(TSEQ / QTILE, BATCH, NSPLIT);
    attn_mma_kernel<<<ag, 128, smem_bytes>>>();

    combine_kernel<<<BT_TOTAL / 128, 128>>>(out);
}